// round 1
// baseline (speedup 1.0000x reference)
#include <cuda_runtime.h>
#include <cstdint>

#define N_NODES 8192
#define F_DIM   512
#define H1_DIM  32
#define H2_DIM  16
#define E_NNZ   131072

// ---------------- scratch (static device globals; no allocs) ----------------
__device__ float g_xw0[N_NODES * H1_DIM];   // X @ W0
__device__ float g_h1 [N_NODES * H1_DIM];   // spmm(A, XW0)   (pre-relu)
__device__ float g_t  [N_NODES * 48];       // relu(h1) @ [W1|W2|W3] packed
__device__ float g_s  [N_NODES * 48];       // spmm(A, t) packed
__device__ float g_z  [N_NODES * H2_DIM];   // final latent

// ---------------- K0: zero accumulators (graph-replay safe) ----------------
__global__ void k_zero() {
    int i = blockIdx.x * blockDim.x + threadIdx.x;
    float4 zz = make_float4(0.f, 0.f, 0.f, 0.f);
    if (i < N_NODES * H1_DIM / 4) reinterpret_cast<float4*>(g_h1)[i] = zz;
    if (i < N_NODES * 48 / 4)     reinterpret_cast<float4*>(g_s)[i]  = zz;
}

// ---------------- K1: XW0 = features @ W0  (warp per row, lane = out col) ----
__global__ void k_xw0(const float* __restrict__ X, const float* __restrict__ W0) {
    int warp = (blockIdx.x * blockDim.x + threadIdx.x) >> 5;
    int lane = threadIdx.x & 31;
    if (warp >= N_NODES) return;
    const float4* xrow = reinterpret_cast<const float4*>(X + (size_t)warp * F_DIM);
    float acc = 0.f;
#pragma unroll 8
    for (int k4 = 0; k4 < F_DIM / 4; k4++) {
        float4 f = xrow[k4];
        int k = k4 * 4;
        acc = fmaf(f.x, W0[(k + 0) * H1_DIM + lane], acc);
        acc = fmaf(f.y, W0[(k + 1) * H1_DIM + lane], acc);
        acc = fmaf(f.z, W0[(k + 2) * H1_DIM + lane], acc);
        acc = fmaf(f.w, W0[(k + 3) * H1_DIM + lane], acc);
    }
    g_xw0[warp * H1_DIM + lane] = acc;
}

// ---------------- K2: h1 = spmm(A, XW0)  (warp per edge) -------------------
__global__ void k_spmm1(const int* __restrict__ rows, const int* __restrict__ cols,
                        const float* __restrict__ vals) {
    int e = (blockIdx.x * blockDim.x + threadIdx.x) >> 5;
    int lane = threadIdx.x & 31;
    if (e >= E_NNZ) return;
    int r = rows[e];
    int c = cols[e];
    float v = vals[e];
    atomicAdd(&g_h1[r * H1_DIM + lane], v * g_xw0[c * H1_DIM + lane]);
}

// ---------------- K3: t = relu(h1) @ [W1|W2|W3]  (thread per row) ----------
__global__ void k_dense2(const float* __restrict__ W1, const float* __restrict__ W2,
                         const float* __restrict__ W3) {
    __shared__ float sW[32 * 48];
    int tid = threadIdx.x;
    for (int i = tid; i < 32 * 16; i += 256) {
        int k = i >> 4, j = i & 15;
        sW[k * 48 + j]      = W1[i];
        sW[k * 48 + 16 + j] = W2[i];
        sW[k * 48 + 32 + j] = W3[i];
    }
    __syncthreads();
    int row = blockIdx.x * 256 + tid;
    float h[32];
    const float4* hr = reinterpret_cast<const float4*>(g_h1 + row * 32);
#pragma unroll
    for (int q = 0; q < 8; q++) {
        float4 v = hr[q];
        h[4 * q + 0] = fmaxf(v.x, 0.f);
        h[4 * q + 1] = fmaxf(v.y, 0.f);
        h[4 * q + 2] = fmaxf(v.z, 0.f);
        h[4 * q + 3] = fmaxf(v.w, 0.f);
    }
    float* outp = g_t + (size_t)row * 48;
#pragma unroll 4
    for (int j = 0; j < 48; j++) {
        float acc = 0.f;
#pragma unroll
        for (int k = 0; k < 32; k++) acc = fmaf(h[k], sW[k * 48 + j], acc);
        outp[j] = acc;
    }
}

// ---------------- K4: s = spmm(A, t)  (thread per (edge, col48)) -----------
__global__ void k_spmm3(const int* __restrict__ rows, const int* __restrict__ cols,
                        const float* __restrict__ vals) {
    unsigned g = blockIdx.x * blockDim.x + threadIdx.x;   // < E*48
    unsigned e = g / 48u;
    unsigned c = g - e * 48u;
    if (e >= E_NNZ) return;
    int r  = rows[e];
    int cl = cols[e];
    float v = vals[e];
    atomicAdd(&g_s[r * 48 + c], v * g_t[cl * 48 + c]);
}

// ---------------- K5: softmax heads + double reparameterization ------------
__global__ void k_combine(const float* __restrict__ s1, const float* __restrict__ s2) {
    int tid  = threadIdx.x;
    int row  = blockIdx.x * 16 + (tid >> 4);
    int lane = tid & 15;

    float ex = g_s[row * 48 + lane];
    float x2 = g_s[row * 48 + 16 + lane];
    float x3 = g_s[row * 48 + 32 + lane];

    // softmax over groups of 16 lanes (groups are 16-aligned, xor<16 stays inside)
    float m2 = x2, m3 = x3;
#pragma unroll
    for (int d = 8; d; d >>= 1) {
        m2 = fmaxf(m2, __shfl_xor_sync(0xffffffffu, m2, d));
        m3 = fmaxf(m3, __shfl_xor_sync(0xffffffffu, m3, d));
    }
    float e2 = __expf(x2 - m2), e3 = __expf(x3 - m3);
    float q2 = e2, q3 = e3;
#pragma unroll
    for (int d = 8; d; d >>= 1) {
        q2 += __shfl_xor_sync(0xffffffffu, q2, d);
        q3 += __shfl_xor_sync(0xffffffffu, q3, d);
    }
    float p2 = e2 / q2;          // z_log_en
    float p3 = e3 / q3;          // z_log_he
    float z_en = __expf(p2);
    float z_he = 0.1f * __expf(p3);
    float z_enn = z_en + s1[row * 16 + lane] * z_he;
    float z = ex + s2[row * 16 + lane] * z_enn;
    g_z[row * 16 + lane] = z;
}

// ---------------- K6: out = z @ z^T  (128x128 tile, f32x2 FFMA2) -----------
__device__ __forceinline__ void fma_f32x2(unsigned long long& d,
                                          unsigned long long a,
                                          unsigned long long b) {
    asm("fma.rn.f32x2 %0, %1, %2, %0;" : "+l"(d) : "l"(a), "l"(b));
}

#define ZPAD 18   // 18 floats/row: 18*t mod 32 is a permutation over t=0..15 -> no LDS bank conflicts

__global__ void __launch_bounds__(256, 1) k_zzt(float* __restrict__ out) {
    __shared__ float szi[128 * ZPAD];
    __shared__ float szj[128 * ZPAD];

    int i0 = blockIdx.y * 128;
    int j0 = blockIdx.x * 128;
    int tid = threadIdx.x;

    // Load both 128x16 tiles (512 float4 each; 2 per thread), coalesced.
#pragma unroll
    for (int q = 0; q < 2; q++) {
        int idx = q * 256 + tid;
        int r = idx >> 2;
        int c = (idx & 3) * 4;
        float4 vi = *reinterpret_cast<const float4*>(&g_z[(i0 + r) * 16 + c]);
        float4 vj = *reinterpret_cast<const float4*>(&g_z[(j0 + r) * 16 + c]);
        // smem rows are 72B-strided (8B aligned) -> two float2 stores
        *reinterpret_cast<float2*>(&szi[r * ZPAD + c])     = make_float2(vi.x, vi.y);
        *reinterpret_cast<float2*>(&szi[r * ZPAD + c + 2]) = make_float2(vi.z, vi.w);
        *reinterpret_cast<float2*>(&szj[r * ZPAD + c])     = make_float2(vj.x, vj.y);
        *reinterpret_cast<float2*>(&szj[r * ZPAD + c + 2]) = make_float2(vj.z, vj.w);
    }
    __syncthreads();

    int ti = tid >> 4;    // 0..15  (i group)
    int tj = tid & 15;    // 0..15  (j group)

    unsigned long long acc[8][8];
#pragma unroll
    for (int r = 0; r < 8; r++)
#pragma unroll
        for (int c = 0; c < 8; c++) acc[r][c] = 0ull;

#pragma unroll
    for (int kp = 0; kp < 8; kp++) {
        unsigned long long a[8], b[8];
#pragma unroll
        for (int r = 0; r < 8; r++)
            a[r] = *reinterpret_cast<const unsigned long long*>(
                &szi[(ti + 16 * r) * ZPAD + 2 * kp]);
#pragma unroll
        for (int c = 0; c < 8; c++)
            b[c] = *reinterpret_cast<const unsigned long long*>(
                &szj[(tj + 16 * c) * ZPAD + 2 * kp]);
#pragma unroll
        for (int r = 0; r < 8; r++)
#pragma unroll
            for (int c = 0; c < 8; c++) fma_f32x2(acc[r][c], a[r], b[c]);
    }

    // epilogue: horizontal add of the f32x2 pair, store (2x64B per warp STG)
#pragma unroll
    for (int r = 0; r < 8; r++) {
        int i = i0 + ti + 16 * r;
        float* orow = out + (size_t)i * N_NODES + j0;
#pragma unroll
        for (int c = 0; c < 8; c++) {
            unsigned long long u = acc[r][c];
            float lo = __int_as_float((int)(u & 0xffffffffull));
            float hi = __int_as_float((int)(u >> 32));
            orow[tj + 16 * c] = lo + hi;
        }
    }
}

// ---------------- launcher ---------------------------------------------------
extern "C" void kernel_launch(void* const* d_in, const int* in_sizes, int n_in,
                              void* d_out, int out_size) {
    const float* features = (const float*)d_in[0];
    const int*   adj_rows = (const int*)  d_in[1];
    const int*   adj_cols = (const int*)  d_in[2];
    const float* adj_val  = (const float*)d_in[3];
    const float* W0       = (const float*)d_in[4];
    const float* W1       = (const float*)d_in[5];
    const float* W2       = (const float*)d_in[6];
    const float* W3       = (const float*)d_in[7];
    const float* sample_1 = (const float*)d_in[8];
    const float* sample_2 = (const float*)d_in[9];
    float* out = (float*)d_out;

    k_zero<<<(N_NODES * 48 / 4 + 255) / 256, 256>>>();
    k_xw0<<<N_NODES * 32 / 256, 256>>>(features, W0);
    k_spmm1<<<E_NNZ * 32 / 256, 256>>>(adj_rows, adj_cols, adj_val);
    k_dense2<<<N_NODES / 256, 256>>>(W1, W2, W3);
    k_spmm3<<<(E_NNZ * 48) / 256, 256>>>(adj_rows, adj_cols, adj_val);
    k_combine<<<N_NODES / 16, 256>>>(sample_1, sample_2);

    dim3 grid(N_NODES / 128, N_NODES / 128);
    k_zzt<<<grid, 256>>>(out);
}